// round 2
// baseline (speedup 1.0000x reference)
#include <cuda_runtime.h>
#include <cuda_bf16.h>
#include <math.h>

#define B_ 32
#define T_ 2048
#define E_ 1024
#define A_ 1024
#define D_ 1024

#define TM 64
#define TN 64
#define TK 16

typedef unsigned long long ull;

// Scratch (no allocations allowed): device globals.
__device__ float g_dec_proj[B_ * A_];   // W_dec @ dec + b_enc, per (b, a)
__device__ float g_energy[B_ * T_];     // raw (unmasked) energies

// ---------------- packed f32x2 helpers (FFMA2 path, PTX-only) ----------------
__device__ __forceinline__ ull pk2(float x, float y) {
    ull r; asm("mov.b64 %0, {%1, %2};" : "=l"(r) : "f"(x), "f"(y)); return r;
}
__device__ __forceinline__ float2 upk2(ull a) {
    float2 f; asm("mov.b64 {%0, %1}, %2;" : "=f"(f.x), "=f"(f.y) : "l"(a)); return f;
}
__device__ __forceinline__ void ffma2(ull& d, ull a, ull b) {
    asm("fma.rn.f32x2 %0, %1, %2, %3;" : "=l"(d) : "l"(a), "l"(b), "l"(d));
}

// ---------------- kernel 1: dec_proj[b,a] = dec[b,:] . W_dec[:,a] + b_enc[a] ----
__global__ __launch_bounds__(256) void dec_proj_kernel(
    const float* __restrict__ dec_out, const float* __restrict__ W_dec,
    const float* __restrict__ b_enc)
{
    int b = blockIdx.y;
    int a = blockIdx.x * 256 + threadIdx.x;
    __shared__ float ds[D_];
    for (int i = threadIdx.x; i < D_; i += 256) ds[i] = dec_out[b * D_ + i];
    __syncthreads();
    float s = b_enc[a];
    #pragma unroll 8
    for (int d = 0; d < D_; ++d) s += ds[d] * W_dec[(size_t)d * A_ + a];
    g_dec_proj[b * A_ + a] = s;
}

// ---------------- kernel 2: fused  energy[b,t] = v . tanh(enc@W_enc + dec_proj) ----
// Block: 256 threads, computes TM=64 rows (t) for one b. Loops A in TN=64 chunks,
// K-tiled over E with both tiles staged in SMEM. Inner product uses packed
// fma.rn.f32x2: enc values duplicated into both halves at fill time, W pre-packed
// as (n, n+1) pairs, so each k-step is 1 LDS.128 + 4 LDS.64 + 8 FFMA2 per thread.
__global__ __launch_bounds__(256) void energy_kernel(
    const float* __restrict__ enc, const float* __restrict__ W,
    const float* __restrict__ v)
{
    int b  = blockIdx.y;
    int t0 = blockIdx.x * TM;
    const float* encB = enc + ((size_t)b * T_ + t0) * E_;

    __shared__ __align__(16) ull  As2[TK][TM + 1];   // enc, each float duplicated (pad kills STS conflicts)
    __shared__ __align__(16) ull  Bsp[TK][TN / 2];   // W pairs (n, n+1)
    __shared__ float red[TM][17];

    int tid = threadIdx.x;
    int mg  = tid >> 4;           // As fill: row group 0..15
    int kg  = tid & 15;           // As fill: k 0..15
    int nb  = tid & 31;           // Bs fill: pair index 0..31
    int kb  = tid >> 5;           // Bs fill: k 0..7
    int tm  = (tid >> 4) * 4;     // this thread's 4 rows
    int tn2 = (tid & 15) * 2;     // this thread's 2 column-pairs (4 cols)

    float rowsum[4] = {0.f, 0.f, 0.f, 0.f};

    for (int chunk = 0; chunk < A_ / TN; ++chunk) {
        int a0 = chunk * TN;
        ull acc01[4] = {0ull, 0ull, 0ull, 0ull};
        ull acc23[4] = {0ull, 0ull, 0ull, 0ull};

        for (int k0 = 0; k0 < E_; k0 += TK) {
            #pragma unroll
            for (int r = 0; r < 4; ++r) {
                int m = mg + r * 16;
                float x = encB[(size_t)m * E_ + k0 + kg];
                As2[kg][m] = pk2(x, x);
            }
            #pragma unroll
            for (int r = 0; r < 2; ++r) {
                int k = kb + r * 8;
                float2 w = *(const float2*)&W[(size_t)(k0 + k) * A_ + a0 + 2 * nb];
                Bsp[k][nb] = pk2(w.x, w.y);
            }
            __syncthreads();
            #pragma unroll
            for (int k = 0; k < TK; ++k) {
                ulonglong2 bb = *(const ulonglong2*)&Bsp[k][tn2];
                #pragma unroll
                for (int i = 0; i < 4; ++i) {
                    ull aa = As2[k][tm + i];
                    ffma2(acc01[i], aa, bb.x);
                    ffma2(acc23[i], aa, bb.y);
                }
            }
            __syncthreads();
        }

        // epilogue for this A-chunk: tanh(acc + dec_proj) * v, fold into row sums
        int acol = a0 + (tid & 15) * 4;
        float dp0 = g_dec_proj[b * A_ + acol + 0];
        float dp1 = g_dec_proj[b * A_ + acol + 1];
        float dp2 = g_dec_proj[b * A_ + acol + 2];
        float dp3 = g_dec_proj[b * A_ + acol + 3];
        float v0 = v[acol + 0], v1 = v[acol + 1], v2 = v[acol + 2], v3 = v[acol + 3];
        #pragma unroll
        for (int i = 0; i < 4; ++i) {
            float2 c01 = upk2(acc01[i]);
            float2 c23 = upk2(acc23[i]);
            rowsum[i] += tanhf(c01.x + dp0) * v0 + tanhf(c01.y + dp1) * v1
                       + tanhf(c23.x + dp2) * v2 + tanhf(c23.y + dp3) * v3;
        }
    }

    // reduce the 16 column-group partials per row
    #pragma unroll
    for (int i = 0; i < 4; ++i) red[tm + i][tid & 15] = rowsum[i];
    __syncthreads();
    if (tid < TM) {
        float s = 0.f;
        #pragma unroll
        for (int q = 0; q < 16; ++q) s += red[tid][q];
        g_energy[b * T_ + t0 + tid] = s;
    }
}

// ---------------- kernel 3: masked (0/1 mask, NOT -inf) softmax over T ----------
__global__ __launch_bounds__(256) void softmax_kernel(
    const int* __restrict__ x_lens, float* __restrict__ att)
{
    int b = blockIdx.x, tid = threadIdx.x;
    __shared__ float sm[T_];
    __shared__ float red[256];
    int len = x_lens[b];

    float mx = -3.4e38f;
    for (int t = tid; t < T_; t += 256) {
        float e = g_energy[b * T_ + t];
        e = (t < len) ? e : 0.0f;      // reference multiplies by 0/1 mask
        sm[t] = e;
        mx = fmaxf(mx, e);
    }
    red[tid] = mx; __syncthreads();
    for (int s = 128; s > 0; s >>= 1) {
        if (tid < s) red[tid] = fmaxf(red[tid], red[tid + s]);
        __syncthreads();
    }
    mx = red[0];
    __syncthreads();

    float lsum = 0.f;
    for (int t = tid; t < T_; t += 256) {
        float e = expf(sm[t] - mx);
        sm[t] = e;
        lsum += e;
    }
    red[tid] = lsum; __syncthreads();
    for (int s = 128; s > 0; s >>= 1) {
        if (tid < s) red[tid] += red[tid + s];
        __syncthreads();
    }
    float inv = 1.0f / red[0];
    for (int t = tid; t < T_; t += 256) att[b * T_ + t] = sm[t] * inv;
}

// ---------------- kernel 4: context[b,e] = sum_t enc[b,t,e] * att[b,t] ----------
__global__ __launch_bounds__(256) void context_kernel(
    const float* __restrict__ enc, const float* __restrict__ att,
    float* __restrict__ ctx)
{
    int b = blockIdx.y;
    int e = blockIdx.x * 256 + threadIdx.x;
    __shared__ float as_[T_];
    for (int t = threadIdx.x; t < T_; t += 256) as_[t] = att[b * T_ + t];
    __syncthreads();
    const float* ep = enc + (size_t)b * T_ * E_ + e;
    float s = 0.f;
    #pragma unroll 16
    for (int t = 0; t < T_; ++t) s += ep[(size_t)t * E_] * as_[t];
    ctx[b * E_ + e] = s;
}

// ---------------- launch -------------------------------------------------------
extern "C" void kernel_launch(void* const* d_in, const int* in_sizes, int n_in,
                              void* d_out, int out_size)
{
    const float* enc     = (const float*)d_in[0];  // [B,T,E]
    const int*   x_lens  = (const int*)  d_in[1];  // [B]
    const float* dec_out = (const float*)d_in[2];  // [B,1,D]
    // d_in[3] = att_weights_step — unused by the reference
    const float* W_enc   = (const float*)d_in[4];  // [E,A]
    const float* b_enc   = (const float*)d_in[5];  // [A]
    const float* W_dec   = (const float*)d_in[6];  // [D,A]
    const float* v       = (const float*)d_in[7];  // [A]

    float* ctx = (float*)d_out;            // [B,1,E] = 32768 floats
    float* att = (float*)d_out + B_ * E_;  // [B,T]   = 65536 floats

    dec_proj_kernel<<<dim3(A_ / 256, B_), 256>>>(dec_out, W_dec, b_enc);
    energy_kernel <<<dim3(T_ / TM, B_), 256>>>(enc, W_enc, v);
    softmax_kernel<<<B_, 256>>>(x_lens, att);
    context_kernel<<<dim3(E_ / 256, B_), 256>>>(enc, att, ctx);
}

// round 4
// speedup vs baseline: 2.6146x; 2.6146x over previous
#include <cuda_runtime.h>
#include <cuda_bf16.h>
#include <math.h>
#include <stdint.h>

#define B_ 32
#define T_ 2048
#define E_ 1024
#define A_ 1024
#define D_ 1024

typedef unsigned int u32;
typedef unsigned long long u64;

// ---------------- scratch (device globals; allocations forbidden) --------------
__device__ __align__(256) __nv_bfloat16 g_enc_hi[(size_t)B_ * T_ * E_];
__device__ __align__(256) __nv_bfloat16 g_enc_lo[(size_t)B_ * T_ * E_];
__device__ __align__(256) __nv_bfloat16 g_Wt_hi[A_ * E_];   // W^T [A,E], K-contiguous
__device__ __align__(256) __nv_bfloat16 g_Wt_lo[A_ * E_];
__device__ float g_dec_proj[B_ * A_];
__device__ float g_energy[B_ * T_];

// ---------------- PTX helpers (baseline ISA only: sm_80-class) ------------------
__device__ __forceinline__ u32 smem_u32(const void* p) {
    u32 a; asm("{ .reg .u64 t; cvta.to.shared.u64 t, %1; cvt.u32.u64 %0, t; }" : "=r"(a) : "l"(p));
    return a;
}
__device__ __forceinline__ void cpa16(u32 dst, const void* src) {
    asm volatile("cp.async.cg.shared.global [%0], [%1], 16;" :: "r"(dst), "l"(src));
}
#define CPA_COMMIT()  asm volatile("cp.async.commit_group;" ::: "memory")
#define CPA_WAIT(n)   asm volatile("cp.async.wait_group %0;" :: "n"(n) : "memory")

__device__ __forceinline__ void ldsm4(u32* r, u32 addr) {
    asm volatile("ldmatrix.sync.aligned.m8n8.x4.shared.b16 {%0,%1,%2,%3}, [%4];"
        : "=r"(r[0]), "=r"(r[1]), "=r"(r[2]), "=r"(r[3]) : "r"(addr));
}
__device__ __forceinline__ void mma_bf16(float* c, const u32* a, const u32* b) {
    asm volatile("mma.sync.aligned.m16n8k16.row.col.f32.bf16.bf16.f32 "
        "{%0,%1,%2,%3}, {%4,%5,%6,%7}, {%8,%9}, {%0,%1,%2,%3};"
        : "+f"(c[0]), "+f"(c[1]), "+f"(c[2]), "+f"(c[3])
        : "r"(a[0]), "r"(a[1]), "r"(a[2]), "r"(a[3]), "r"(b[0]), "r"(b[1]));
}

// tanh via 2 MUFU: tanh(x) = (e - 1)/(e + 1), e = 2^(2x*log2e)
__device__ __forceinline__ float fast_tanh(float x) {
    float xa = fminf(fmaxf(x, -12.0f), 12.0f);
    float e;
    asm("ex2.approx.f32 %0, %1;" : "=f"(e) : "f"(xa * 2.8853900817779268f));
    float r;
    asm("rcp.approx.f32 %0, %1;" : "=f"(r) : "f"(e + 1.0f));
    return (e - 1.0f) * r;
}

// ---------------- pass 0a: enc fp32 -> bf16 hi/lo ------------------------------
__global__ __launch_bounds__(256) void convert_enc_kernel(const float* __restrict__ enc) {
    size_t i = ((size_t)blockIdx.x * 256 + threadIdx.x) * 4;
    float4 x = *(const float4*)(enc + i);
    __nv_bfloat16 h0 = __float2bfloat16(x.x), h1 = __float2bfloat16(x.y);
    __nv_bfloat16 h2 = __float2bfloat16(x.z), h3 = __float2bfloat16(x.w);
    __nv_bfloat16 l0 = __float2bfloat16(x.x - __bfloat162float(h0));
    __nv_bfloat16 l1 = __float2bfloat16(x.y - __bfloat162float(h1));
    __nv_bfloat16 l2 = __float2bfloat16(x.z - __bfloat162float(h2));
    __nv_bfloat16 l3 = __float2bfloat16(x.w - __bfloat162float(h3));
    *(__nv_bfloat162*)(g_enc_hi + i)     = __nv_bfloat162(h0, h1);
    *(__nv_bfloat162*)(g_enc_hi + i + 2) = __nv_bfloat162(h2, h3);
    *(__nv_bfloat162*)(g_enc_lo + i)     = __nv_bfloat162(l0, l1);
    *(__nv_bfloat162*)(g_enc_lo + i + 2) = __nv_bfloat162(l2, l3);
}

// ---------------- pass 0b: W_enc [E,A] -> W^T [A,E] bf16 hi/lo ------------------
__global__ __launch_bounds__(256) void convert_wt_kernel(const float* __restrict__ W) {
    int idx = blockIdx.x * 256 + threadIdx.x;      // output-linear over [A,E]
    int a = idx >> 10, e = idx & 1023;
    float x = W[(size_t)e * A_ + a];
    __nv_bfloat16 h = __float2bfloat16(x);
    g_Wt_hi[idx] = h;
    g_Wt_lo[idx] = __float2bfloat16(x - __bfloat162float(h));
}

// ---------------- pass 1: dec_proj[b,a] = dec[b,:] . W_dec[:,a] + b_enc[a] ------
__global__ __launch_bounds__(256) void dec_proj_kernel(
    const float* __restrict__ dec_out, const float* __restrict__ W_dec,
    const float* __restrict__ b_enc)
{
    int b = blockIdx.y;
    int a = blockIdx.x * 256 + threadIdx.x;
    __shared__ float ds[D_];
    for (int i = threadIdx.x; i < D_; i += 256) ds[i] = dec_out[b * D_ + i];
    __syncthreads();
    float s = b_enc[a];
    #pragma unroll 8
    for (int d = 0; d < D_; ++d) s += ds[d] * W_dec[(size_t)d * A_ + a];
    g_dec_proj[b * A_ + a] = s;
}

// ---------------- pass 2: mma.sync split-bf16 GEMM + tanh + v-reduce ------------
// 256 thr = 8 warps (4M x 2N). CTA tile M=128 x N=128 per chunk, 8 N-chunks.
// K staged in 32-wide double-buffered cp.async stages; rows padded 64B->80B
// (conflict-free ldmatrix, no swizzle). 3 MMA splits: hi*hi + hi*lo + lo*hi.
#define KC 32
#define NSTAGE (E_/KC)           // 32
#define ROWB 80                  // 64B data + 16B pad
#define SPLIT_SZ (128 * ROWB)    // 10240
#define STG_SZ (4 * SPLIT_SZ)    // Ahi, Alo, Bhi, Blo
#define ST_AH 0
#define ST_AL SPLIT_SZ
#define ST_BH (2 * SPLIT_SZ)
#define ST_BL (3 * SPLIT_SZ)
#define OF_DP (2 * STG_SZ)       // 81920
#define OF_V  (OF_DP + 4096)
#define OF_RED (OF_V + 4096)
#define SMEM_TOTAL (OF_RED + 1024)   // 91136

__device__ __forceinline__ void stage_in(u32 sb, int st, int kc, int a0,
                                         const char* encH, const char* encL, int tid)
{
    const u32 base = sb + st * STG_SZ;
    const int kbyte = kc * 64;                 // 32 bf16 = 64B along k
    #pragma unroll
    for (int r = 0; r < 2; ++r) {
        int c   = tid + r * 256;               // 0..511 chunks of 16B per split
        int row = c >> 2, col = (c & 3) * 16;
        u32 so  = (u32)(row * ROWB + col);
        size_t ga = (size_t)row * 2048 + kbyte + col;
        cpa16(base + ST_AH + so, encH + ga);
        cpa16(base + ST_AL + so, encL + ga);
        size_t gb = (size_t)(a0 + row) * 2048 + kbyte + col;
        cpa16(base + ST_BH + so, (const char*)g_Wt_hi + gb);
        cpa16(base + ST_BL + so, (const char*)g_Wt_lo + gb);
    }
}

__global__ __launch_bounds__(256, 1) void energy_kernel(const float* __restrict__ v) {
    extern __shared__ char smem[];
    u32 sb = smem_u32(smem);
    const int tid  = threadIdx.x;
    const int lane = tid & 31, wid = tid >> 5;
    const int wm = wid >> 1, wn = wid & 1;
    const int m0 = blockIdx.x * 128;           // flattened (b*T + t) row base
    const int b  = m0 >> 11;

    float* dp_s = (float*)(smem + OF_DP);
    float* v_s  = (float*)(smem + OF_V);
    float* red  = (float*)(smem + OF_RED);
    for (int i = tid; i < A_; i += 256) {
        dp_s[i] = g_dec_proj[b * A_ + i];
        v_s[i]  = v[i];
    }
    __syncthreads();

    const char* encH = (const char*)g_enc_hi + (size_t)m0 * 2048;
    const char* encL = (const char*)g_enc_lo + (size_t)m0 * 2048;

    // ldmatrix lane addressing (constant per thread)
    const u32 a_row = (u32)(wm * 32 + (lane & 15));
    const u32 a_kof = (u32)(((lane >> 4) & 1) * 8);
    const u32 b_row = (u32)(wn * 64 + (lane & 7) + ((lane >> 4) & 1) * 8);
    const u32 b_kof = (u32)(((lane >> 3) & 1) * 8);

    float rowsum[4] = {0.f, 0.f, 0.f, 0.f};

    for (int ch = 0; ch < 8; ++ch) {
        const int a0 = ch * 128;
        float c[2][8][4];
        #pragma unroll
        for (int tm = 0; tm < 2; ++tm)
            #pragma unroll
            for (int tn = 0; tn < 8; ++tn)
                #pragma unroll
                for (int q = 0; q < 4; ++q) c[tm][tn][q] = 0.f;

        stage_in(sb, 0, 0, a0, encH, encL, tid);
        CPA_COMMIT();

        for (int kc = 0; kc < NSTAGE; ++kc) {
            if (kc + 1 < NSTAGE) {
                stage_in(sb, (kc + 1) & 1, kc + 1, a0, encH, encL, tid);
                CPA_COMMIT();
                CPA_WAIT(1);
            } else {
                CPA_WAIT(0);
            }
            __syncthreads();

            const u32 base = sb + (kc & 1) * STG_SZ;
            #pragma unroll
            for (int ks = 0; ks < 2; ++ks) {
                const u32 kb = (u32)(ks * 16);
                u32 ah[2][4], al[2][4];
                #pragma unroll
                for (int tm = 0; tm < 2; ++tm) {
                    u32 off = (a_row + tm * 16) * ROWB + (kb + a_kof) * 2;
                    ldsm4(ah[tm], base + ST_AH + off);
                    ldsm4(al[tm], base + ST_AL + off);
                }
                u32 bh[8][2], bl[8][2];
                #pragma unroll
                for (int p = 0; p < 4; ++p) {
                    u32 off = (b_row + p * 16) * ROWB + (kb + b_kof) * 2;
                    u32 t[4];
                    ldsm4(t, base + ST_BH + off);
                    bh[2*p][0] = t[0]; bh[2*p][1] = t[1];
                    bh[2*p+1][0] = t[2]; bh[2*p+1][1] = t[3];
                    ldsm4(t, base + ST_BL + off);
                    bl[2*p][0] = t[0]; bl[2*p][1] = t[1];
                    bl[2*p+1][0] = t[2]; bl[2*p+1][1] = t[3];
                }
                #pragma unroll
                for (int tm = 0; tm < 2; ++tm)
                    #pragma unroll
                    for (int tn = 0; tn < 8; ++tn) {
                        mma_bf16(c[tm][tn], ah[tm], bh[tn]);
                        mma_bf16(c[tm][tn], ah[tm], bl[tn]);
                        mma_bf16(c[tm][tn], al[tm], bh[tn]);
                    }
            }
            __syncthreads();
        }

        // epilogue: tanh(c + dec_proj) . v folded into per-row partials
        #pragma unroll
        for (int tm = 0; tm < 2; ++tm)
            #pragma unroll
            for (int tn = 0; tn < 8; ++tn) {
                int n = a0 + wn * 64 + tn * 8 + 2 * (lane & 3);
                float d0 = dp_s[n], d1 = dp_s[n + 1];
                float v0 = v_s[n],  v1 = v_s[n + 1];
                rowsum[tm*2+0] += fast_tanh(c[tm][tn][0] + d0) * v0
                                + fast_tanh(c[tm][tn][1] + d1) * v1;
                rowsum[tm*2+1] += fast_tanh(c[tm][tn][2] + d0) * v0
                                + fast_tanh(c[tm][tn][3] + d1) * v1;
            }
    }

    // reduce across the 4 lanes of each quad (they cover disjoint n-columns)
    #pragma unroll
    for (int i = 0; i < 4; ++i) {
        float s = rowsum[i];
        s += __shfl_xor_sync(0xffffffffu, s, 1);
        s += __shfl_xor_sync(0xffffffffu, s, 2);
        rowsum[i] = s;
    }
    if ((lane & 3) == 0) {
        int r0 = lane >> 2;
        int rb = wn * 128 + wm * 32;
        red[rb + r0]          = rowsum[0];
        red[rb + r0 + 8]      = rowsum[1];
        red[rb + 16 + r0]     = rowsum[2];
        red[rb + 16 + r0 + 8] = rowsum[3];
    }
    __syncthreads();
    if (tid < 128) g_energy[m0 + tid] = red[tid] + red[128 + tid];
}

// ---------------- pass 3: masked (0/1) softmax over T ---------------------------
__global__ __launch_bounds__(256) void softmax_kernel(
    const int* __restrict__ x_lens, float* __restrict__ att)
{
    int b = blockIdx.x, tid = threadIdx.x;
    __shared__ float sm[T_];
    __shared__ float red[256];
    int len = x_lens[b];

    float mx = -3.4e38f;
    for (int t = tid; t < T_; t += 256) {
        float e = g_energy[b * T_ + t];
        e = (t < len) ? e : 0.0f;      // reference multiplies by 0/1 mask
        sm[t] = e;
        mx = fmaxf(mx, e);
    }
    red[tid] = mx; __syncthreads();
    for (int s = 128; s > 0; s >>= 1) {
        if (tid < s) red[tid] = fmaxf(red[tid], red[tid + s]);
        __syncthreads();
    }
    mx = red[0];
    __syncthreads();

    float lsum = 0.f;
    for (int t = tid; t < T_; t += 256) {
        float e = expf(sm[t] - mx);
        sm[t] = e;
        lsum += e;
    }
    red[tid] = lsum; __syncthreads();
    for (int s = 128; s > 0; s >>= 1) {
        if (tid < s) red[tid] += red[tid + s];
        __syncthreads();
    }
    float inv = 1.0f / red[0];
    for (int t = tid; t < T_; t += 256) att[b * T_ + t] = sm[t] * inv;
}

// ---------------- pass 4: context[b,e] = sum_t enc[b,t,e] * att[b,t] ------------
__global__ __launch_bounds__(128) void context_kernel(
    const float* __restrict__ enc, const float* __restrict__ att,
    float* __restrict__ ctx)
{
    int b = blockIdx.y;
    int e = blockIdx.x * 128 + threadIdx.x;
    __shared__ float as_[T_];
    for (int t = threadIdx.x; t < T_; t += 128) as_[t] = att[b * T_ + t];
    __syncthreads();
    const float* ep = enc + (size_t)b * T_ * E_ + e;
    float s = 0.f;
    #pragma unroll 8
    for (int t = 0; t < T_; ++t) s += ep[(size_t)t * E_] * as_[t];
    ctx[b * E_ + e] = s;
}

// ---------------- launch -------------------------------------------------------
extern "C" void kernel_launch(void* const* d_in, const int* in_sizes, int n_in,
                              void* d_out, int out_size)
{
    const float* enc     = (const float*)d_in[0];  // [B,T,E]
    const int*   x_lens  = (const int*)  d_in[1];  // [B]
    const float* dec_out = (const float*)d_in[2];  // [B,1,D]
    // d_in[3] att_weights_step: unused by reference
    const float* W_enc   = (const float*)d_in[4];  // [E,A]
    const float* b_enc   = (const float*)d_in[5];  // [A]
    const float* W_dec   = (const float*)d_in[6];  // [D,A]
    const float* v       = (const float*)d_in[7];  // [A]

    float* ctx = (float*)d_out;            // [B,1,E]
    float* att = (float*)d_out + B_ * E_;  // [B,T]

    cudaFuncSetAttribute(energy_kernel,
                         cudaFuncAttributeMaxDynamicSharedMemorySize, SMEM_TOTAL);

    convert_enc_kernel<<<(B_ * T_ * E_) / (256 * 4), 256>>>(enc);
    convert_wt_kernel <<<(A_ * E_) / 256, 256>>>(W_enc);
    dec_proj_kernel   <<<dim3(A_ / 256, B_), 256>>>(dec_out, W_dec, b_enc);
    energy_kernel     <<<(B_ * T_) / 128, 256, SMEM_TOTAL>>>(v);
    softmax_kernel    <<<B_, 256>>>(x_lens, att);
    context_kernel    <<<dim3(E_ / 128, B_), 128>>>(enc, att, ctx);
}

// round 6
// speedup vs baseline: 3.2263x; 1.2339x over previous
#include <cuda_runtime.h>
#include <cuda_bf16.h>
#include <math.h>
#include <stdint.h>

#define B_ 32
#define T_ 2048
#define E_ 1024
#define A_ 1024
#define D_ 1024

typedef unsigned int u32;
typedef unsigned long long u64;

// ---------------- scratch (device globals; allocations forbidden) --------------
__device__ __align__(256) __nv_bfloat16 g_enc_hi[(size_t)B_ * T_ * E_];
__device__ __align__(256) __nv_bfloat16 g_enc_lo[(size_t)B_ * T_ * E_];
__device__ __align__(256) __nv_bfloat16 g_Wt_hi[A_ * E_];   // W^T [A,E], K-contiguous
__device__ __align__(256) __nv_bfloat16 g_Wt_lo[A_ * E_];
__device__ float g_dec_proj[B_ * A_];
__device__ float g_energy[B_ * T_];
__device__ float g_ctx_part[4 * B_ * E_];

// ---------------- PTX helpers (baseline ISA only: sm_80-class) ------------------
__device__ __forceinline__ u32 smem_u32(const void* p) {
    u32 a; asm("{ .reg .u64 t; cvta.to.shared.u64 t, %1; cvt.u32.u64 %0, t; }" : "=r"(a) : "l"(p));
    return a;
}
__device__ __forceinline__ void cpa16(u32 dst, const void* src) {
    asm volatile("cp.async.cg.shared.global [%0], [%1], 16;" :: "r"(dst), "l"(src));
}
#define CPA_COMMIT()  asm volatile("cp.async.commit_group;" ::: "memory")
#define CPA_WAIT(n)   asm volatile("cp.async.wait_group %0;" :: "n"(n) : "memory")

__device__ __forceinline__ void ldsm4(u32* r, u32 addr) {
    asm volatile("ldmatrix.sync.aligned.m8n8.x4.shared.b16 {%0,%1,%2,%3}, [%4];"
        : "=r"(r[0]), "=r"(r[1]), "=r"(r[2]), "=r"(r[3]) : "r"(addr));
}
__device__ __forceinline__ void mma_bf16(float* c, const u32* a, const u32* b) {
    asm volatile("mma.sync.aligned.m16n8k16.row.col.f32.bf16.bf16.f32 "
        "{%0,%1,%2,%3}, {%4,%5,%6,%7}, {%8,%9}, {%0,%1,%2,%3};"
        : "+f"(c[0]), "+f"(c[1]), "+f"(c[2]), "+f"(c[3])
        : "r"(a[0]), "r"(a[1]), "r"(a[2]), "r"(a[3]), "r"(b[0]), "r"(b[1]));
}

// tanh via 2 MUFU: tanh(x) = (e - 1)/(e + 1), e = 2^(2x*log2e)
__device__ __forceinline__ float fast_tanh(float x) {
    float xa = fminf(fmaxf(x, -12.0f), 12.0f);
    float e;
    asm("ex2.approx.f32 %0, %1;" : "=f"(e) : "f"(xa * 2.8853900817779268f));
    float r;
    asm("rcp.approx.f32 %0, %1;" : "=f"(r) : "f"(e + 1.0f));
    return (e - 1.0f) * r;
}

// ---------------- pass 0a: enc fp32 -> bf16 hi/lo ------------------------------
__global__ __launch_bounds__(256) void convert_enc_kernel(const float* __restrict__ enc) {
    size_t i = ((size_t)blockIdx.x * 256 + threadIdx.x) * 4;
    float4 x = *(const float4*)(enc + i);
    __nv_bfloat16 h0 = __float2bfloat16(x.x), h1 = __float2bfloat16(x.y);
    __nv_bfloat16 h2 = __float2bfloat16(x.z), h3 = __float2bfloat16(x.w);
    __nv_bfloat16 l0 = __float2bfloat16(x.x - __bfloat162float(h0));
    __nv_bfloat16 l1 = __float2bfloat16(x.y - __bfloat162float(h1));
    __nv_bfloat16 l2 = __float2bfloat16(x.z - __bfloat162float(h2));
    __nv_bfloat16 l3 = __float2bfloat16(x.w - __bfloat162float(h3));
    *(__nv_bfloat162*)(g_enc_hi + i)     = __nv_bfloat162(h0, h1);
    *(__nv_bfloat162*)(g_enc_hi + i + 2) = __nv_bfloat162(h2, h3);
    *(__nv_bfloat162*)(g_enc_lo + i)     = __nv_bfloat162(l0, l1);
    *(__nv_bfloat162*)(g_enc_lo + i + 2) = __nv_bfloat162(l2, l3);
}

// ---------------- pass 0b: W_enc [E,A] -> W^T [A,E] bf16 hi/lo ------------------
__global__ __launch_bounds__(256) void convert_wt_kernel(const float* __restrict__ W) {
    int idx = blockIdx.x * 256 + threadIdx.x;      // output-linear over [A,E]
    int a = idx >> 10, e = idx & 1023;
    float x = W[(size_t)e * A_ + a];
    __nv_bfloat16 h = __float2bfloat16(x);
    g_Wt_hi[idx] = h;
    g_Wt_lo[idx] = __float2bfloat16(x - __bfloat162float(h));
}

// ---------------- pass 1: dec_proj[b,a] = dec[b,:] . W_dec[:,a] + b_enc[a] ------
__global__ __launch_bounds__(256) void dec_proj_kernel(
    const float* __restrict__ dec_out, const float* __restrict__ W_dec,
    const float* __restrict__ b_enc)
{
    int b = blockIdx.y;
    int a = blockIdx.x * 256 + threadIdx.x;
    __shared__ float ds[D_];
    for (int i = threadIdx.x; i < D_; i += 256) ds[i] = dec_out[b * D_ + i];
    __syncthreads();
    float s = b_enc[a];
    #pragma unroll 8
    for (int d = 0; d < D_; ++d) s += ds[d] * W_dec[(size_t)d * A_ + a];
    g_dec_proj[b * A_ + a] = s;
}

// ---------------- pass 2: mma.sync split-bf16 GEMM + tanh + v-reduce ------------
// 256 thr = 8 warps (4M x 2N), 2 CTAs/SM. CTA tile M=128 x N=128/chunk, 8 chunks.
// K in 32-wide double-buffered cp.async stages, flat prefetch across chunks
// (epilogue overlaps next chunk's DMA). Rows padded 64B->80B => conflict-free
// ldmatrix. 3 MMA splits: hi*hi + hi*lo + lo*hi.
#define KC 32
#define NSTAGE (E_/KC)           // 32 per chunk, 256 flat
#define ROWB 80                  // 64B data + 16B pad
#define SPLIT_SZ (128 * ROWB)    // 10240
#define STG_SZ (4 * SPLIT_SZ)    // Ahi, Alo, Bhi, Blo
#define ST_AH 0
#define ST_AL SPLIT_SZ
#define ST_BH (2 * SPLIT_SZ)
#define ST_BL (3 * SPLIT_SZ)
#define OF_DP (2 * STG_SZ)       // 81920
#define OF_V  (OF_DP + 4096)
#define OF_RED (OF_V + 4096)
#define SMEM_TOTAL (OF_RED + 1024)   // 91136 -> 2 CTAs/SM fit in 228KB

__device__ __forceinline__ void stage_in(u32 sb, int st, int kc, int a0,
                                         const char* encH, const char* encL, int tid)
{
    const u32 base = sb + st * STG_SZ;
    const int kbyte = kc * 64;                 // 32 bf16 = 64B along k
    #pragma unroll
    for (int r = 0; r < 2; ++r) {
        int c   = tid + r * 256;               // 512 chunks of 16B per split
        int row = c >> 2, col = (c & 3) * 16;
        u32 so  = (u32)(row * ROWB + col);
        size_t ga = (size_t)row * 2048 + kbyte + col;
        cpa16(base + ST_AH + so, encH + ga);
        cpa16(base + ST_AL + so, encL + ga);
        size_t gb = (size_t)(a0 + row) * 2048 + kbyte + col;
        cpa16(base + ST_BH + so, (const char*)g_Wt_hi + gb);
        cpa16(base + ST_BL + so, (const char*)g_Wt_lo + gb);
    }
}

__global__ __launch_bounds__(256, 2) void energy_kernel(const float* __restrict__ v) {
    extern __shared__ char smem[];
    u32 sb = smem_u32(smem);
    const int tid  = threadIdx.x;
    const int lane = tid & 31, wid = tid >> 5;
    const int wm = wid >> 1, wn = wid & 1;
    const int m0 = blockIdx.x * 128;           // flattened (b*T + t) row base
    const int b  = m0 >> 11;

    float* dp_s = (float*)(smem + OF_DP);
    float* v_s  = (float*)(smem + OF_V);
    float* red  = (float*)(smem + OF_RED);
    for (int i = tid; i < A_; i += 256) {
        dp_s[i] = g_dec_proj[b * A_ + i];
        v_s[i]  = v[i];
    }

    const char* encH = (const char*)g_enc_hi + (size_t)m0 * 2048;
    const char* encL = (const char*)g_enc_lo + (size_t)m0 * 2048;

    // ldmatrix lane addressing (constant per thread)
    const u32 a_row = (u32)(wm * 32 + (lane & 15));
    const u32 a_kof = (u32)(((lane >> 4) & 1) * 8);
    const u32 b_row = (u32)(wn * 64 + (lane & 7) + ((lane >> 4) & 1) * 8);
    const u32 b_kof = (u32)(((lane >> 3) & 1) * 8);

    float rowsum[4] = {0.f, 0.f, 0.f, 0.f};

    stage_in(sb, 0, 0, 0, encH, encL, tid);
    CPA_COMMIT();

    for (int ch = 0; ch < 8; ++ch) {
        const int a0 = ch * 128;
        float c[2][8][4];
        #pragma unroll
        for (int tm = 0; tm < 2; ++tm)
            #pragma unroll
            for (int tn = 0; tn < 8; ++tn)
                #pragma unroll
                for (int q = 0; q < 4; ++q) c[tm][tn][q] = 0.f;

        for (int kc = 0; kc < NSTAGE; ++kc) {
            const int s = ch * NSTAGE + kc;           // flat stage index
            if (s + 1 < 8 * NSTAGE) {
                const int ns = s + 1;
                stage_in(sb, ns & 1, ns & (NSTAGE - 1), (ns >> 5) * 128,
                         encH, encL, tid);
                CPA_COMMIT();
                CPA_WAIT(1);
            } else {
                CPA_WAIT(0);
            }
            __syncthreads();

            const u32 base = sb + (s & 1) * STG_SZ;
            #pragma unroll
            for (int ks = 0; ks < 2; ++ks) {
                const u32 kb = (u32)(ks * 16);
                u32 ah[2][4], al[2][4];
                #pragma unroll
                for (int tm = 0; tm < 2; ++tm) {
                    u32 off = (a_row + tm * 16) * ROWB + (kb + a_kof) * 2;
                    ldsm4(ah[tm], base + ST_AH + off);
                    ldsm4(al[tm], base + ST_AL + off);
                }
                #pragma unroll
                for (int p = 0; p < 4; ++p) {
                    u32 off = (b_row + p * 16) * ROWB + (kb + b_kof) * 2;
                    u32 th[4], tl[4];
                    ldsm4(th, base + ST_BH + off);
                    ldsm4(tl, base + ST_BL + off);
                    #pragma unroll
                    for (int tm = 0; tm < 2; ++tm) {
                        mma_bf16(c[tm][2*p],   ah[tm], th);
                        mma_bf16(c[tm][2*p],   ah[tm], tl);
                        mma_bf16(c[tm][2*p],   al[tm], th);
                        mma_bf16(c[tm][2*p+1], ah[tm], th + 2);
                        mma_bf16(c[tm][2*p+1], ah[tm], tl + 2);
                        mma_bf16(c[tm][2*p+1], al[tm], th + 2);
                    }
                }
            }
            __syncthreads();
        }

        // epilogue (register-only): tanh(c + dec_proj) . v into per-row partials
        #pragma unroll
        for (int tm = 0; tm < 2; ++tm)
            #pragma unroll
            for (int tn = 0; tn < 8; ++tn) {
                int n = a0 + wn * 64 + tn * 8 + 2 * (lane & 3);
                float d0 = dp_s[n], d1 = dp_s[n + 1];
                float v0 = v_s[n],  v1 = v_s[n + 1];
                rowsum[tm*2+0] += fast_tanh(c[tm][tn][0] + d0) * v0
                                + fast_tanh(c[tm][tn][1] + d1) * v1;
                rowsum[tm*2+1] += fast_tanh(c[tm][tn][2] + d0) * v0
                                + fast_tanh(c[tm][tn][3] + d1) * v1;
            }
    }

    // reduce across the 4 lanes of each quad (disjoint n-columns)
    #pragma unroll
    for (int i = 0; i < 4; ++i) {
        float s = rowsum[i];
        s += __shfl_xor_sync(0xffffffffu, s, 1);
        s += __shfl_xor_sync(0xffffffffu, s, 2);
        rowsum[i] = s;
    }
    if ((lane & 3) == 0) {
        int r0 = lane >> 2;
        int rb = wn * 128 + wm * 32;
        red[rb + r0]          = rowsum[0];
        red[rb + r0 + 8]      = rowsum[1];
        red[rb + 16 + r0]     = rowsum[2];
        red[rb + 16 + r0 + 8] = rowsum[3];
    }
    __syncthreads();
    if (tid < 128) g_energy[m0 + tid] = red[tid] + red[128 + tid];
}

// ---------------- pass 3: masked (0/1) softmax over T ---------------------------
__global__ __launch_bounds__(256) void softmax_kernel(
    const int* __restrict__ x_lens, float* __restrict__ att)
{
    int b = blockIdx.x, tid = threadIdx.x;
    __shared__ float sm[T_];
    __shared__ float red[256];
    int len = x_lens[b];

    float mx = -3.4e38f;
    for (int t = tid; t < T_; t += 256) {
        float e = g_energy[b * T_ + t];
        e = (t < len) ? e : 0.0f;      // reference multiplies by 0/1 mask
        sm[t] = e;
        mx = fmaxf(mx, e);
    }
    red[tid] = mx; __syncthreads();
    for (int s = 128; s > 0; s >>= 1) {
        if (tid < s) red[tid] = fmaxf(red[tid], red[tid + s]);
        __syncthreads();
    }
    mx = red[0];
    __syncthreads();

    float lsum = 0.f;
    for (int t = tid; t < T_; t += 256) {
        float e = expf(sm[t] - mx);
        sm[t] = e;
        lsum += e;
    }
    red[tid] = lsum; __syncthreads();
    for (int s = 128; s > 0; s >>= 1) {
        if (tid < s) red[tid] += red[tid + s];
        __syncthreads();
    }
    float inv = 1.0f / red[0];
    for (int t = tid; t < T_; t += 256) att[b * T_ + t] = sm[t] * inv;
}

// ---------------- pass 4: context partials over T segments ----------------------
__global__ __launch_bounds__(128) void context_part_kernel(
    const float* __restrict__ enc, const float* __restrict__ att)
{
    int b = blockIdx.y, seg = blockIdx.z;
    int e = blockIdx.x * 128 + threadIdx.x;
    __shared__ float as_[T_ / 4];
    int t0 = seg * (T_ / 4);
    for (int t = threadIdx.x; t < T_ / 4; t += 128) as_[t] = att[b * T_ + t0 + t];
    __syncthreads();
    const float* ep = enc + ((size_t)b * T_ + t0) * E_ + e;
    float s = 0.f;
    #pragma unroll 8
    for (int t = 0; t < T_ / 4; ++t) s += ep[(size_t)t * E_] * as_[t];
    g_ctx_part[((size_t)seg * B_ + b) * E_ + e] = s;
}

__global__ __launch_bounds__(256) void context_reduce_kernel(float* __restrict__ ctx) {
    int i = blockIdx.x * 256 + threadIdx.x;      // over B_*E_
    ctx[i] = g_ctx_part[i] + g_ctx_part[B_ * E_ + i]
           + g_ctx_part[2 * B_ * E_ + i] + g_ctx_part[3 * B_ * E_ + i];
}

// ---------------- launch -------------------------------------------------------
extern "C" void kernel_launch(void* const* d_in, const int* in_sizes, int n_in,
                              void* d_out, int out_size)
{
    const float* enc     = (const float*)d_in[0];  // [B,T,E]
    const int*   x_lens  = (const int*)  d_in[1];  // [B]
    const float* dec_out = (const float*)d_in[2];  // [B,1,D]
    // d_in[3] att_weights_step: unused by reference
    const float* W_enc   = (const float*)d_in[4];  // [E,A]
    const float* b_enc   = (const float*)d_in[5];  // [A]
    const float* W_dec   = (const float*)d_in[6];  // [D,A]
    const float* v       = (const float*)d_in[7];  // [A]

    float* ctx = (float*)d_out;            // [B,1,E]
    float* att = (float*)d_out + B_ * E_;  // [B,T]

    cudaFuncSetAttribute(energy_kernel,
                         cudaFuncAttributeMaxDynamicSharedMemorySize, SMEM_TOTAL);

    convert_enc_kernel<<<(B_ * T_ * E_) / (256 * 4), 256>>>(enc);
    convert_wt_kernel <<<(A_ * E_) / 256, 256>>>(W_enc);
    dec_proj_kernel   <<<dim3(A_ / 256, B_), 256>>>(dec_out, W_dec, b_enc);
    energy_kernel     <<<(B_ * T_) / 128, 256, SMEM_TOTAL>>>(v);
    softmax_kernel    <<<B_, 256>>>(x_lens, att);
    context_part_kernel<<<dim3(E_ / 128, B_, 4), 128>>>(enc, att);
    context_reduce_kernel<<<(B_ * E_) / 256, 256>>>(ctx);
}